// round 6
// baseline (speedup 1.0000x reference)
#include <cuda_runtime.h>
#include <math.h>

#define Bb 16
#define Ff 128
#define Nn 2048
#define BN (Bb*Nn)          // 32768
#define TOT (Bb*Ff*Nn)      // 4194304
#define NBLK 512            // k_fused grid size

// scratch (allocation-free: __device__ globals)
__device__ float g_s[BN];
__device__ float g_E[BN];
__device__ float g_psum[NBLK];
__device__ float g_psq[NBLK];

// ---------------------------------------------------------------------------
// Pass 1: s[b,n] = sum_f v[f]*emb[b,f,n]; per-block partial sum/sumsq written
// to g_psum/g_psq (NO atomics — same-address RED serialization was the tail).
// Block = 512 threads = 8 f-chunks (16 f each) x 64 n-positions. Grid = 512.
// ---------------------------------------------------------------------------
__global__ void __launch_bounds__(512) k_fused(const float* __restrict__ emb,
                                               const float* __restrict__ v) {
    __shared__ float sv[Ff];
    __shared__ float spart[512];
    __shared__ float red_sum[16];
    __shared__ float red_sq[16];

    int tid = threadIdx.x;
    if (tid < Ff) sv[tid] = v[tid];
    __syncthreads();

    int b  = blockIdx.x >> 5;          // 0..15
    int ng = blockIdx.x & 31;          // 0..31 (group of 64 n)
    int nl = tid & 63;                 // 0..63
    int fc = tid >> 6;                 // 0..7  (f-chunk of 16)
    int n  = ng * 64 + nl;

    const float* p  = emb + ((size_t)(b * Ff + fc * 16)) * Nn + n;
    const float* pv = sv + fc * 16;

    float s = 0.f, sum = 0.f, sq = 0.f;
#pragma unroll
    for (int f = 0; f < 16; f++) {
        float x = __ldg(p + (size_t)f * Nn);
        s   = fmaf(pv[f], x, s);
        sum += x;
        sq  = fmaf(x, x, sq);
    }
    spart[tid] = s;
    __syncthreads();
    if (tid < 64) {
        float tot = 0.f;
#pragma unroll
        for (int c = 0; c < 8; c++) tot += spart[c * 64 + tid];
        g_s[b * Nn + ng * 64 + tid] = tot;
    }

    // block reduce sum & sq -> plain per-block stores
    int lane = tid & 31;
    int wid  = tid >> 5;
#pragma unroll
    for (int o = 16; o > 0; o >>= 1) {
        sum += __shfl_xor_sync(0xffffffffu, sum, o);
        sq  += __shfl_xor_sync(0xffffffffu, sq, o);
    }
    if (lane == 0) { red_sum[wid] = sum; red_sq[wid] = sq; }
    __syncthreads();
    if (wid == 0) {
        float rs = (lane < 16) ? red_sum[lane] : 0.f;
        float rq = (lane < 16) ? red_sq[lane]  : 0.f;
#pragma unroll
        for (int o = 8; o > 0; o >>= 1) {
            rs += __shfl_xor_sync(0xffffffffu, rs, o);
            rq += __shfl_xor_sync(0xffffffffu, rq, o);
        }
        if (lane == 0) {
            g_psum[blockIdx.x] = rs;
            g_psq[blockIdx.x]  = rq;
        }
    }
}

// ---------------------------------------------------------------------------
// Pass 2: every block redundantly reduces the 512 partials (L2-resident),
// computes scale, then E[n] = exp(-(s[n]*scale + bias/2)).
// ---------------------------------------------------------------------------
__global__ void __launch_bounds__(256) k_exp(const float* __restrict__ bias) {
    __shared__ float red_sum[8];
    __shared__ float red_sq[8];
    __shared__ float sh_scale, sh_hb;

    int tid  = threadIdx.x;
    int lane = tid & 31;
    int wid  = tid >> 5;

    // reduce 512 partials with 256 threads (2 each)
    float sum = g_psum[tid] + g_psum[tid + 256];
    float sq  = g_psq[tid]  + g_psq[tid + 256];
#pragma unroll
    for (int o = 16; o > 0; o >>= 1) {
        sum += __shfl_xor_sync(0xffffffffu, sum, o);
        sq  += __shfl_xor_sync(0xffffffffu, sq, o);
    }
    if (lane == 0) { red_sum[wid] = sum; red_sq[wid] = sq; }
    __syncthreads();
    if (tid == 0) {
        double ds = 0.0, dq = 0.0;
#pragma unroll
        for (int w = 0; w < 8; w++) { ds += (double)red_sum[w]; dq += (double)red_sq[w]; }
        double m   = (double)TOT;
        double var = (dq - ds * ds / m) / (m - 1.0);
        sh_scale = (float)(1.0 / sqrt(var));
        sh_hb    = 0.5f * bias[0];
    }
    __syncthreads();

    int idx = blockIdx.x * 256 + tid;
    float t = fmaf(g_s[idx], sh_scale, sh_hb);
    g_E[idx] = __expf(-t);
}

// ---------------------------------------------------------------------------
// Pass 3: out[b,i,j] = 1 / (1 + E_i * E_j). 4 rows per block, plain stores
// (proven fastest). This kernel sits at the LTS write cap (~6.4 TB/s).
// ---------------------------------------------------------------------------
__device__ __forceinline__ float frcp(float x) {
    float r;
    asm("rcp.approx.f32 %0, %1;" : "=f"(r) : "f"(x));
    return r;
}

__global__ void __launch_bounds__(512) k_main(float* __restrict__ out) {
    int r0 = blockIdx.x << 2;          // first of 4 rows
    int b  = r0 >> 11;

    const float4* Erow = (const float4*)(g_E + (size_t)b * Nn);
    float4 ej = __ldg(Erow + threadIdx.x);

    float p0 = __ldg(g_E + r0);
    float p1 = __ldg(g_E + r0 + 1);
    float p2 = __ldg(g_E + r0 + 2);
    float p3 = __ldg(g_E + r0 + 3);

    float4 o0, o1, o2, o3;
    o0.x = frcp(fmaf(p0, ej.x, 1.f)); o0.y = frcp(fmaf(p0, ej.y, 1.f));
    o0.z = frcp(fmaf(p0, ej.z, 1.f)); o0.w = frcp(fmaf(p0, ej.w, 1.f));
    o1.x = frcp(fmaf(p1, ej.x, 1.f)); o1.y = frcp(fmaf(p1, ej.y, 1.f));
    o1.z = frcp(fmaf(p1, ej.z, 1.f)); o1.w = frcp(fmaf(p1, ej.w, 1.f));
    o2.x = frcp(fmaf(p2, ej.x, 1.f)); o2.y = frcp(fmaf(p2, ej.y, 1.f));
    o2.z = frcp(fmaf(p2, ej.z, 1.f)); o2.w = frcp(fmaf(p2, ej.w, 1.f));
    o3.x = frcp(fmaf(p3, ej.x, 1.f)); o3.y = frcp(fmaf(p3, ej.y, 1.f));
    o3.z = frcp(fmaf(p3, ej.z, 1.f)); o3.w = frcp(fmaf(p3, ej.w, 1.f));

    float4* orow = (float4*)(out + (size_t)r0 * Nn) + threadIdx.x;
    orow[0]          = o0;
    orow[Nn / 4]     = o1;
    orow[Nn / 2]     = o2;
    orow[3 * Nn / 4] = o3;
}

extern "C" void kernel_launch(void* const* d_in, const int* in_sizes, int n_in,
                              void* d_out, int out_size) {
    // inputs: adj_in [B,N,N] (unused), emb_in [B,F,N], v [F], b [1]
    const float* emb  = (const float*)d_in[1];
    const float* v    = (const float*)d_in[2];
    const float* bias = (const float*)d_in[3];
    float* out = (float*)d_out;

    k_fused<<<NBLK, 512>>>(emb, v);
    k_exp<<<BN / 256, 256>>>(bias);
    k_main<<<BN / 4, 512>>>(out);
}